// round 8
// baseline (speedup 1.0000x reference)
#include <cuda_runtime.h>

// Problem constants
#define B_ 8
#define C_ 256
#define N_ 16384
#define K_ 128

// Decomposition: CTA = (batch, 64-channel slice, 1-of-9 N interleave)
#define SLICE_C 64
#define NSLICE 4                // C_/SLICE_C
#define NS 9                    // N interleave -> 8*4*9 = 288 CTAs, 2/SM
#define TN 64                   // points per chunk
#define TPB 512
#define NCHUNKS (N_ / TN)       // 256 chunks, round-robin over NS
#define TROW 68                 // padded smem row stride
#define TAB_U (K_ * TROW)       // smem table uints
#define TABC (K_ * SLICE_C)     // compact dump uints per CTA (8192)
#define NGROUP (B_ * NSLICE)    // 32 reduction groups

// Compact per-CTA partials: 288 x 32KB = 9.4 MB (L2-resident).
__device__ unsigned int g_scratch[NGROUP * NS * TABC];
__device__ int g_count[NGROUP];   // zero-init; each finisher resets its own

// Monotone float -> uint key: unsigned order == float order.
__device__ __forceinline__ unsigned int fkey(float f) {
    int i = __float_as_int(f);
    return (i >= 0) ? ((unsigned int)i | 0x80000000u) : ~(unsigned int)i;
}
__device__ __forceinline__ float funkey(unsigned int k) {
    unsigned int i = (k & 0x80000000u) ? (k & 0x7FFFFFFFu) : ~k;
    return __int_as_float((int)i);
}

// Single fused kernel: transpose + per-CTA segment-max + finisher reduction.
__global__ __launch_bounds__(TPB, 2)
void seg_fused(const float* __restrict__ pf, const int* __restrict__ cids,
               float* __restrict__ out_pf, float* __restrict__ out_seg) {
    extern __shared__ unsigned int smem[];
    unsigned int* tab = smem;                          // [K][TROW]
    float* tile = (float*)(smem + TAB_U);              // [TN][TROW] point-major
    int* scid = (int*)(tile + TN * TROW);              // TN ids
    __shared__ int s_fin;

    const int tid = threadIdx.x;
    const int b = blockIdx.y;
    const int cslice = blockIdx.x / NS;                // 0..3
    const int ns = blockIdx.x - cslice * NS;           // 0..8
    const int gidx = b * NSLICE + cslice;              // reduction group

    {   // init table
        uint4 z = make_uint4(0u, 0u, 0u, 0u);
        uint4* t4 = (uint4*)tab;
        #pragma unroll
        for (int i = tid; i < TAB_U / 4; i += TPB) t4[i] = z;
    }

    const float* src = pf + (size_t)b * C_ * N_ + (size_t)cslice * SLICE_C * N_;
    const int* cidp = cids + b * N_;

    const int cnt = (NCHUNKS / NS) + (ns < (NCHUNKS % NS) ? 1 : 0);  // 29 or 28

    // Loader: thread owns point ln, channel quads cg4 and cg4+32 (in-slice)
    const int ln = tid & 63;
    const int cg4 = (tid >> 6) * 4;     // 0,4,...,28
    // Consumer: 4 consecutive channels per thread; warp = 2 points
    const int c4 = (tid & 15) * 4;      // 0..60
    const int pb = tid >> 4;            // 0..31

    auto prefetch = [&](int i, float* rr, int& cidr) {
        const int m = ns + NS * i;
        const float* p0 = src + (size_t)cg4 * N_ + m * TN + ln;
        #pragma unroll
        for (int j = 0; j < 4; j++) {
            rr[j]     = __ldcs(p0 + (size_t)j * N_);
            rr[4 + j] = __ldcs(p0 + (size_t)(32 + j) * N_);
        }
        if (tid < TN) cidr = cidp[m * TN + tid];
    };

    float rA[8], rB[8];
    int cidA = 0, cidB = 0;
    prefetch(0, rA, cidA);
    if (cnt > 1) prefetch(1, rB, cidB);

    auto body = [&](int i, float* rr, int& cidr) {
        __syncthreads();                               // prev tile fully consumed
        *(float4*)(tile + ln * TROW + cg4)      = make_float4(rr[0], rr[1], rr[2], rr[3]);
        *(float4*)(tile + ln * TROW + cg4 + 32) = make_float4(rr[4], rr[5], rr[6], rr[7]);
        if (tid < TN) scid[tid] = cidr;
        __syncthreads();                               // tile + scid ready

        if (i + 2 < cnt) prefetch(i + 2, rr, cidr);    // refill freed buffer

        const int n0 = (ns + NS * i) * TN;
        #pragma unroll
        for (int q = 0; q < 2; q++) {
            const int p = pb + q * 32;
            float4 vv = *(const float4*)(tile + p * TROW + c4);
            __stcs((float4*)(out_pf + ((size_t)b * N_ + n0 + p) * C_
                             + cslice * SLICE_C + c4), vv);
            const int cid = scid[p];
            if (cid >= 0) {
                unsigned int* cell = &tab[cid * TROW + c4];
                uint4 cur = *(const uint4*)cell;       // LDS.128 filter read
                unsigned int k0 = fkey(vv.x); if (cur.x < k0) atomicMax(cell + 0, k0);
                unsigned int k1 = fkey(vv.y); if (cur.y < k1) atomicMax(cell + 1, k1);
                unsigned int k2 = fkey(vv.z); if (cur.z < k2) atomicMax(cell + 2, k2);
                unsigned int k3 = fkey(vv.w); if (cur.w < k3) atomicMax(cell + 3, k3);
            }
        }
    };

    int i = 0;
    #pragma unroll 1
    for (; i + 1 < cnt; i += 2) {
        body(i,     rA, cidA);
        body(i + 1, rB, cidB);
    }
    if (i < cnt) body(i, rA, cidA);                    // odd tail
    __syncthreads();

    // compact dump: [K][64] (plain stores -> L2-resident)
    {
        uint4* dst = (uint4*)(g_scratch + (size_t)(gidx * NS + ns) * TABC);
        #pragma unroll
        for (int j = tid; j < TABC / 4; j += TPB) {
            int row = j >> 4;
            int col4 = (j & 15) * 4;
            dst[j] = *(const uint4*)(tab + row * TROW + col4);
        }
    }

    // signal completion; last CTA of the group reduces
    __threadfence();
    __syncthreads();
    if (tid == 0) s_fin = (atomicAdd(&g_count[gidx], 1) == NS - 1);
    __syncthreads();
    if (!s_fin) return;

    __threadfence();                                   // acquire partials
    const uint4* base = (const uint4*)(g_scratch + (size_t)gidx * NS * TABC);
    #pragma unroll 1
    for (int j = tid; j < TABC / 4; j += TPB) {        // 4 outputs/thread
        uint4 mx = base[j];
        #pragma unroll
        for (int s = 1; s < NS; s++) {
            uint4 v = base[j + (size_t)s * (TABC / 4)];
            mx.x = max(mx.x, v.x); mx.y = max(mx.y, v.y);
            mx.z = max(mx.z, v.z); mx.w = max(mx.w, v.w);
        }
        float4 o;
        o.x = mx.x ? funkey(mx.x) : 0.0f;
        o.y = mx.y ? funkey(mx.y) : 0.0f;
        o.z = mx.z ? funkey(mx.z) : 0.0f;
        o.w = mx.w ? funkey(mx.w) : 0.0f;
        int k = j >> 4;
        int cc4 = (j & 15) * 4;
        ((float4*)out_seg)[(((size_t)b * K_ + k) * C_ + cslice * SLICE_C + cc4) >> 2] = o;
    }
    __syncthreads();
    if (tid == 0) g_count[gidx] = 0;                   // reset for next replay
}

extern "C" void kernel_launch(void* const* d_in, const int* in_sizes, int n_in,
                              void* d_out, int out_size) {
    const float* pf = (const float*)d_in[0];      // (B,C,N) f32
    const int* cid  = (const int*)d_in[1];        // (B,N) i32
    float* out      = (float*)d_out;
    float* out_seg  = out;                        // (B*K, C)
    float* out_pf   = out + (size_t)B_ * K_ * C_; // (B*N, C)

    const size_t smem_bytes = (size_t)TAB_U * 4 + (size_t)TN * TROW * 4 + (size_t)TN * 4;
    cudaFuncSetAttribute(seg_fused, cudaFuncAttributeMaxDynamicSharedMemorySize,
                         (int)smem_bytes);

    dim3 grid(NSLICE * NS, B_);                   // 36 x 8 = 288 CTAs, 2/SM
    seg_fused<<<grid, TPB, smem_bytes>>>(pf, cid, out_pf, out_seg);
}

// round 9
// speedup vs baseline: 1.3780x; 1.3780x over previous
#include <cuda_runtime.h>

// Problem constants
#define B_ 8
#define C_ 256
#define N_ 16384
#define K_ 128

// Decomposition: CTA = (batch, 64-channel slice, 1-of-9 N interleave)
#define SLICE_C 64
#define NSLICE 4                // C_/SLICE_C
#define NS 9                    // N interleave -> 8*4*9 = 288 CTAs, 2/SM
#define TN 64                   // points per chunk
#define TPB 512
#define NCHUNKS (N_ / TN)       // 256 chunks, round-robin over NS
#define TROW 68                 // padded row stride (floats/uints)
#define TAB_U (K_ * TROW)       // 8704 uints per-CTA table

// Per-CTA partial tables: 288 x 34.8KB ~= 10 MB.
__device__ unsigned int g_scratch[B_ * NSLICE * NS * TAB_U];

// Monotone float -> uint key: unsigned order == float order.
__device__ __forceinline__ unsigned int fkey(float f) {
    int i = __float_as_int(f);
    return (i >= 0) ? ((unsigned int)i | 0x80000000u) : ~(unsigned int)i;
}
__device__ __forceinline__ float funkey(unsigned int k) {
    unsigned int i = (k & 0x80000000u) ? (k & 0x7FFFFFFFu) : ~k;
    return __int_as_float((int)i);
}

// Phase 1: fused transpose + per-CTA segment-max, 2-deep reg pipeline, 2 CTAs/SM.
__global__ __launch_bounds__(TPB, 2)
void seg_phase1(const float* __restrict__ pf, const int* __restrict__ cids,
                float* __restrict__ out_pf) {
    extern __shared__ unsigned int smem[];
    unsigned int* tab = smem;                          // [K][TROW], 34.8 KB
    float* tile = (float*)(smem + TAB_U);              // [TN][TROW] point-major
    int* scid = (int*)(tile + TN * TROW);              // TN ids

    const int tid = threadIdx.x;
    const int b = blockIdx.y;
    const int cslice = blockIdx.x / NS;                // 0..3
    const int ns = blockIdx.x - cslice * NS;           // 0..8

    {   // init table
        uint4 z = make_uint4(0u, 0u, 0u, 0u);
        uint4* t4 = (uint4*)tab;
        #pragma unroll
        for (int i = tid; i < TAB_U / 4; i += TPB) t4[i] = z;
    }

    const float* src = pf + (size_t)b * C_ * N_ + (size_t)cslice * SLICE_C * N_;
    const int* cidp = cids + b * N_;

    // chunk count for this ns: 256 = 9*28 + 4 -> ns<4 get 29, else 28
    const int cnt = (NCHUNKS / NS) + (ns < (NCHUNKS % NS) ? 1 : 0);

    // Loader: thread owns point ln, channel quads cg4 and cg4+32 (in-slice)
    const int ln = tid & 63;
    const int cg4 = (tid >> 6) * 4;     // 0,4,...,28
    // Consumer: 4 consecutive channels per thread; warp = 2 points
    const int c4 = (tid & 15) * 4;      // 0..60
    const int pb = tid >> 4;            // 0..31

    auto prefetch = [&](int i, float* rr, int& cidr) {
        const int m = ns + NS * i;
        const float* p0 = src + (size_t)cg4 * N_ + m * TN + ln;
        #pragma unroll
        for (int j = 0; j < 4; j++) {
            rr[j]     = __ldcs(p0 + (size_t)j * N_);
            rr[4 + j] = __ldcs(p0 + (size_t)(32 + j) * N_);
        }
        if (tid < TN) cidr = cidp[m * TN + tid];
    };

    float rA[8], rB[8];
    int cidA = 0, cidB = 0;
    prefetch(0, rA, cidA);
    if (cnt > 1) prefetch(1, rB, cidB);

    auto body = [&](int i, float* rr, int& cidr) {
        __syncthreads();                               // prev tile fully consumed
        *(float4*)(tile + ln * TROW + cg4)      = make_float4(rr[0], rr[1], rr[2], rr[3]);
        *(float4*)(tile + ln * TROW + cg4 + 32) = make_float4(rr[4], rr[5], rr[6], rr[7]);
        if (tid < TN) scid[tid] = cidr;
        __syncthreads();                               // tile + scid ready

        if (i + 2 < cnt) prefetch(i + 2, rr, cidr);    // refill freed buffer

        const int n0 = (ns + NS * i) * TN;
        #pragma unroll
        for (int q = 0; q < 2; q++) {
            const int p = pb + q * 32;
            float4 vv = *(const float4*)(tile + p * TROW + c4);
            __stcs((float4*)(out_pf + ((size_t)b * N_ + n0 + p) * C_
                             + cslice * SLICE_C + c4), vv);
            const int cid = scid[p];
            if (cid >= 0) {
                unsigned int* cell = &tab[cid * TROW + c4];
                uint4 cur = *(const uint4*)cell;       // LDS.128 filter read
                unsigned int k0 = fkey(vv.x); if (cur.x < k0) atomicMax(cell + 0, k0);
                unsigned int k1 = fkey(vv.y); if (cur.y < k1) atomicMax(cell + 1, k1);
                unsigned int k2 = fkey(vv.z); if (cur.z < k2) atomicMax(cell + 2, k2);
                unsigned int k3 = fkey(vv.w); if (cur.w < k3) atomicMax(cell + 3, k3);
            }
        }
    };

    int i = 0;
    #pragma unroll 1
    for (; i + 1 < cnt; i += 2) {
        body(i,     rA, cidA);
        body(i + 1, rB, cidB);
    }
    if (i < cnt) body(i, rA, cidA);                    // odd tail
    __syncthreads();

    // dump table (plain stores)
    uint4* dst = (uint4*)(g_scratch
                 + (size_t)((b * NSLICE + cslice) * NS + ns) * TAB_U);
    const uint4* t4 = (const uint4*)tab;
    #pragma unroll
    for (int i2 = tid; i2 < TAB_U / 4; i2 += TPB) dst[i2] = t4[i2];
}

// Phase 2: 4 threads per output quad (3+2+2+2 split of 9 partials), shfl combine.
__global__ void seg_phase2(float* __restrict__ out_seg) {
    int g = blockIdx.x * blockDim.x + threadIdx.x;     // 0 .. 4*B*K*C/4-1
    int j = g >> 2;                                    // output float4 index
    int r = g & 3;                                     // lane-in-quad
    const int PER_B = K_ * C_ / 4;                     // 8192
    int b = j / PER_B;
    int rem = j - b * PER_B;
    int k = rem >> 6;
    int cg = rem & 63;
    int c = cg * 4;
    int slice = c >> 6;
    int cc = c & 63;
    const unsigned int* base = g_scratch
        + (size_t)((b * NSLICE + slice) * NS) * TAB_U + k * TROW + cc;
    int s0 = (r == 0) ? 0 : (1 + 2 * r);               // 0,3,5,7
    int cnt = (r == 0) ? 3 : 2;
    uint4 mx = make_uint4(0u, 0u, 0u, 0u);
    for (int s = s0; s < s0 + cnt; s++) {
        uint4 v = *(const uint4*)(base + (size_t)s * TAB_U);
        mx.x = max(mx.x, v.x); mx.y = max(mx.y, v.y);
        mx.z = max(mx.z, v.z); mx.w = max(mx.w, v.w);
    }
    #pragma unroll
    for (int d = 1; d <= 2; d <<= 1) {
        mx.x = max(mx.x, __shfl_xor_sync(0xFFFFFFFFu, mx.x, d));
        mx.y = max(mx.y, __shfl_xor_sync(0xFFFFFFFFu, mx.y, d));
        mx.z = max(mx.z, __shfl_xor_sync(0xFFFFFFFFu, mx.z, d));
        mx.w = max(mx.w, __shfl_xor_sync(0xFFFFFFFFu, mx.w, d));
    }
    if (r == 0) {
        float4 o;
        o.x = mx.x ? funkey(mx.x) : 0.0f;
        o.y = mx.y ? funkey(mx.y) : 0.0f;
        o.z = mx.z ? funkey(mx.z) : 0.0f;
        o.w = mx.w ? funkey(mx.w) : 0.0f;
        ((float4*)out_seg)[j] = o;
    }
}

extern "C" void kernel_launch(void* const* d_in, const int* in_sizes, int n_in,
                              void* d_out, int out_size) {
    const float* pf = (const float*)d_in[0];      // (B,C,N) f32
    const int* cid  = (const int*)d_in[1];        // (B,N) i32
    float* out      = (float*)d_out;
    float* out_seg  = out;                        // (B*K, C)
    float* out_pf   = out + (size_t)B_ * K_ * C_; // (B*N, C)

    const size_t smem_bytes = (size_t)TAB_U * 4 + (size_t)TN * TROW * 4 + (size_t)TN * 4;
    cudaFuncSetAttribute(seg_phase1, cudaFuncAttributeMaxDynamicSharedMemorySize,
                         (int)smem_bytes);

    dim3 grid(NSLICE * NS, B_);                   // 36 x 8 = 288 CTAs, 2/SM
    seg_phase1<<<grid, TPB, smem_bytes>>>(pf, cid, out_pf);

    const int t2 = 4 * (B_ * K_ * C_ / 4);        // 262144 threads
    seg_phase2<<<t2 / 256, 256>>>(out_seg);
}